// round 7
// baseline (speedup 1.0000x reference)
#include <cuda_runtime.h>
#include <cuda_fp16.h>
#include <math.h>
#include <stdint.h>

#define T_TOK 4096
#define H_DIM 768
#define I_DIM 1152
#define TWO_I 2304
#define E_NUM 8

// ---------------- device-global scratch ------------------------------------
__device__ int    g_count[E_NUM];
__device__ int    g_tok[E_NUM * T_TOK];
__device__ int    g_dst[E_NUM * T_TOK];
__device__ float  g_w  [E_NUM * T_TOK];
__device__ __half g_act[(size_t)E_NUM * T_TOK * I_DIM];  // expert GLU out
__device__ __half g_as [(size_t)T_TOK * I_DIM];          // shared GLU out
__device__ float  g_par[(size_t)T_TOK * 2 * H_DIM];      // per-(t,k) down-proj
__device__ __half g_hx  [(size_t)T_TOK * H_DIM];         // x fp16
__device__ __half g_hwi [(size_t)E_NUM * H_DIM * TWO_I]; // Wi fp16
__device__ __half g_hwo [(size_t)E_NUM * I_DIM * H_DIM]; // Wo fp16
__device__ __half g_hswi[(size_t)TWO_I * H_DIM];         // sWi fp16
__device__ __half g_hswo[(size_t)H_DIM * I_DIM];         // sWo fp16

// ---------------- PTX helpers ------------------------------------------------
__device__ __forceinline__ float silu_f(float v) { return v / (1.f + __expf(-v)); }

__device__ __forceinline__ void mma16(float* c, const uint32_t* a, const uint32_t* b) {
    asm volatile(
        "mma.sync.aligned.m16n8k16.row.col.f32.f16.f16.f32 "
        "{%0,%1,%2,%3},{%4,%5,%6,%7},{%8,%9},{%0,%1,%2,%3};"
        : "+f"(c[0]), "+f"(c[1]), "+f"(c[2]), "+f"(c[3])
        : "r"(a[0]), "r"(a[1]), "r"(a[2]), "r"(a[3]), "r"(b[0]), "r"(b[1]));
}
__device__ __forceinline__ void ldsm4(uint32_t* r, uint32_t a) {
    asm volatile("ldmatrix.sync.aligned.m8n8.x4.shared.b16 {%0,%1,%2,%3}, [%4];"
                 : "=r"(r[0]), "=r"(r[1]), "=r"(r[2]), "=r"(r[3]) : "r"(a));
}
__device__ __forceinline__ void ldsm4t(uint32_t* r, uint32_t a) {
    asm volatile("ldmatrix.sync.aligned.m8n8.x4.trans.shared.b16 {%0,%1,%2,%3}, [%4];"
                 : "=r"(r[0]), "=r"(r[1]), "=r"(r[2]), "=r"(r[3]) : "r"(a));
}
__device__ __forceinline__ void cpa16(uint32_t dst, const void* src) {
    asm volatile("cp.async.cg.shared.global [%0], [%1], 16;" :: "r"(dst), "l"(src));
}
__device__ __forceinline__ void cpa_commit() {
    asm volatile("cp.async.commit_group;" ::: "memory");
}
template <int NWAIT>
__device__ __forceinline__ void cpa_wait() {
    asm volatile("cp.async.wait_group %0;" :: "n"(NWAIT) : "memory");
}

// ---------------- gating ------------------------------------------------------
__global__ void zero_counts_kernel() {
    if (threadIdx.x < E_NUM) g_count[threadIdx.x] = 0;
}

__global__ void gating_kernel(const float* __restrict__ x,
                              const float* __restrict__ gate_w,
                              const float* __restrict__ bias) {
    __shared__ float sgw[E_NUM * H_DIM];
    int tid = threadIdx.x;
    for (int i = tid; i < E_NUM * H_DIM; i += 256) sgw[i] = gate_w[i];
    __syncthreads();

    int warp = tid >> 5, lane = tid & 31;
    int t = blockIdx.x * 8 + warp;
    const float* xr = x + (size_t)t * H_DIM;

    float acc[E_NUM];
#pragma unroll
    for (int e = 0; e < E_NUM; e++) acc[e] = 0.f;
    for (int h = lane; h < H_DIM; h += 32) {
        float xv = xr[h];
#pragma unroll
        for (int e = 0; e < E_NUM; e++) acc[e] += xv * sgw[e * H_DIM + h];
    }
#pragma unroll
    for (int e = 0; e < E_NUM; e++) {
        float v = acc[e];
#pragma unroll
        for (int o = 16; o > 0; o >>= 1) v += __shfl_down_sync(0xffffffffu, v, o);
        acc[e] = v;
    }
    if (lane == 0) {
        float logit[E_NUM];
#pragma unroll
        for (int e = 0; e < E_NUM; e++) logit[e] = 1.f / (1.f + expf(-acc[e]));
        int i0 = 0; float b0 = -1e30f;
#pragma unroll
        for (int e = 0; e < E_NUM; e++) {
            float s = logit[e] + bias[e];
            if (s > b0) { b0 = s; i0 = e; }
        }
        int i1 = 0; float b1 = -1e30f;
#pragma unroll
        for (int e = 0; e < E_NUM; e++) {
            if (e == i0) continue;
            float s = logit[e] + bias[e];
            if (s > b1) { b1 = s; i1 = e; }
        }
        float w0 = logit[i0], w1 = logit[i1];
        float inv = 1.f / (w0 + w1);
        w0 *= inv; w1 *= inv;
        int p0 = atomicAdd(&g_count[i0], 1);
        g_tok[i0 * T_TOK + p0] = t; g_dst[i0 * T_TOK + p0] = 2 * t;     g_w[i0 * T_TOK + p0] = w0;
        int p1 = atomicAdd(&g_count[i1], 1);
        g_tok[i1 * T_TOK + p1] = t; g_dst[i1 * T_TOK + p1] = 2 * t + 1; g_w[i1 * T_TOK + p1] = w1;
    }
}

// ---------------- merged f32->f16 conversion ----------------------------------
#define N8_X   ((long)T_TOK * H_DIM / 8)
#define N8_WI  ((long)E_NUM * H_DIM * TWO_I / 8)
#define N8_WO  ((long)E_NUM * I_DIM * H_DIM / 8)
#define N8_SWI ((long)TWO_I * H_DIM / 8)
#define N8_SWO ((long)H_DIM * I_DIM / 8)
#define N8_TOT (N8_X + N8_WI + N8_WO + N8_SWI + N8_SWO)

__global__ void f2h_all_kernel(const float* __restrict__ x,  const float* __restrict__ wi,
                               const float* __restrict__ wo, const float* __restrict__ swi,
                               const float* __restrict__ swo) {
    long i = (long)blockIdx.x * blockDim.x + threadIdx.x;
    if (i >= N8_TOT) return;
    const float* src; __half* dst; long off;
    if (i < N8_X)                          { src = x;   dst = g_hx;   off = i; }
    else if (i < N8_X + N8_WI)             { src = wi;  dst = g_hwi;  off = i - N8_X; }
    else if (i < N8_X + N8_WI + N8_WO)     { src = wo;  dst = g_hwo;  off = i - N8_X - N8_WI; }
    else if (i < N8_TOT - N8_SWO)          { src = swi; dst = g_hswi; off = i - N8_X - N8_WI - N8_WO; }
    else                                   { src = swo; dst = g_hswo; off = i - (N8_TOT - N8_SWO); }
    const float4* s = (const float4*)src + off * 2;
    float4 a = s[0], b = s[1];
    __half2 h0 = __floats2half2_rn(a.x, a.y);
    __half2 h1 = __floats2half2_rn(a.z, a.w);
    __half2 h2 = __floats2half2_rn(b.x, b.y);
    __half2 h3 = __floats2half2_rn(b.z, b.w);
    uint4 v = { *(uint32_t*)&h0, *(uint32_t*)&h1, *(uint32_t*)&h2, *(uint32_t*)&h3 };
    ((uint4*)dst)[off] = v;
}

// ================= UP GEMM: 128 rows x 64 GLU cols, split-B, BK=32, 256 thr ====
// BL 1 (NT): B=[2I][K] (shared sWi). BL 0 (NN): B=[K][2I] (expert Wi).
// EPI 1: g_as = silu(proj)*gate.  EPI 2: g_act = silu(gate)*proj*w.
#define UP_ASTR  80u
#define UP_ATILE 10240u
#define UP_BT_NT 5120u
#define UP_BT_NN 4608u

template <int BL, int EPI>
__global__ void __launch_bounds__(256, 2)
up_gemm(const __half* __restrict__ Ab, const __half* __restrict__ Bb,
        __half* __restrict__ C) {
    constexpr int K = H_DIM, NC = K / 32;
    constexpr uint32_t BT  = BL ? UP_BT_NT : UP_BT_NN;
    constexpr uint32_t SSB = UP_ATILE + 2 * BT;
    constexpr int GRP = (EPI == 2);

    int e   = GRP ? blockIdx.z : 0;
    int cnt = GRP ? g_count[e] : T_TOK;
    int bm  = blockIdx.y * 128;
    if (bm >= cnt) return;
    int c0  = blockIdx.x * 64;

    extern __shared__ char smc[];
    uint32_t smaddr = (uint32_t)__cvta_generic_to_shared(smc);
    int tid = threadIdx.x;

    // ---- A staging: row = tid>>1, segs (tid&1)*2 + {0,1}
    int am = tid >> 1, as0 = (tid & 1) * 2;
    int apos = bm + am;
    long arow;
    if (GRP) arow = g_tok[e * T_TOK + ((apos < cnt) ? apos : (cnt - 1))];
    else     arow = apos;
    const __half* aSrc = Ab + (size_t)arow * K + as0 * 8;
    uint32_t aDst = (uint32_t)am * UP_ASTR + as0 * 16;

    // ---- B staging (two halves: proj / gate)
    const __half* bSrc;
    uint32_t bDst;
    if (BL) {   // NT: rows (bh*I + c0 + r) of [2I][K]
        int bh = tid >> 7, bnr = (tid >> 1) & 63, bs0 = (tid & 1) * 2;
        bSrc = Bb + (size_t)(bh * I_DIM + c0 + bnr) * K + bs0 * 8;
        bDst = UP_ATILE + (uint32_t)bh * UP_BT_NT + (uint32_t)bnr * UP_ASTR + bs0 * 16;
    } else {    // NN: [K][2I]
        int bh = tid >> 7, bkr = (tid >> 2) & 31, bs0 = (tid & 3) * 2;
        bSrc = Bb + (size_t)e * K * TWO_I + (size_t)bkr * TWO_I + bh * I_DIM + c0 + bs0 * 8;
        bDst = UP_ATILE + (uint32_t)bh * UP_BT_NN + (uint32_t)bkr * 144 + bs0 * 16;
    }

    float acc[4][4][4];
#pragma unroll
    for (int i = 0; i < 4; i++)
#pragma unroll
        for (int j = 0; j < 4; j++)
#pragma unroll
            for (int q = 0; q < 4; q++) acc[i][j][q] = 0.f;

    // ---- prologue: 2 stages
#pragma unroll
    for (int s = 0; s < 2; s++) {
        uint32_t base = smaddr + s * SSB;
        cpa16(base + aDst,      aSrc + s * 32);
        cpa16(base + aDst + 16, aSrc + s * 32 + 8);
        if (BL) {
            cpa16(base + bDst,      bSrc + s * 32);
            cpa16(base + bDst + 16, bSrc + s * 32 + 8);
        } else {
            cpa16(base + bDst,      bSrc + (size_t)s * 32 * TWO_I);
            cpa16(base + bDst + 16, bSrc + (size_t)s * 32 * TWO_I + 8);
        }
        cpa_commit();
    }

    int warp = tid >> 5, lane = tid & 31;
    int wm = warp >> 2, wn = warp & 3;

    uint32_t aLd = (uint32_t)(wm * 64 + (lane & 15)) * UP_ASTR + (lane >> 4) * 16;
    uint32_t bLdNT = UP_ATILE + (uint32_t)(wn * 16 + (lane & 7) + ((lane >> 4) * 8)) * UP_ASTR +
                     ((lane >> 3) & 1) * 16;
    uint32_t bLdNN = UP_ATILE + (uint32_t)(lane & 15) * 144 + (wn * 2 + (lane >> 4)) * 16;

    // ---- mainloop
    for (int c = 0; c < NC; c++) {
        cpa_wait<1>();
        __syncthreads();

        int pf = c + 2;
        if (pf < NC) {
            uint32_t base = smaddr + (uint32_t)(pf % 3) * SSB;
            cpa16(base + aDst,      aSrc + pf * 32);
            cpa16(base + aDst + 16, aSrc + pf * 32 + 8);
            if (BL) {
                cpa16(base + bDst,      bSrc + pf * 32);
                cpa16(base + bDst + 16, bSrc + pf * 32 + 8);
            } else {
                cpa16(base + bDst,      bSrc + (size_t)pf * 32 * TWO_I);
                cpa16(base + bDst + 16, bSrc + (size_t)pf * 32 * TWO_I + 8);
            }
        }
        cpa_commit();

        uint32_t sbase = smaddr + (uint32_t)(c % 3) * SSB;

        // load ALL fragments for both ks before any MMA (latency overlap)
        uint32_t af[2][4][4], bf[2][2][4];
#pragma unroll
        for (int mi = 0; mi < 4; mi++)
            ldsm4(af[0][mi], sbase + aLd + mi * (16 * UP_ASTR));
#pragma unroll
        for (int t = 0; t < 2; t++) {
            if (BL) ldsm4(bf[0][t], sbase + bLdNT + t * UP_BT_NT);
            else    ldsm4t(bf[0][t], sbase + bLdNN + t * UP_BT_NN);
        }
#pragma unroll
        for (int mi = 0; mi < 4; mi++)
            ldsm4(af[1][mi], sbase + aLd + mi * (16 * UP_ASTR) + 32);
#pragma unroll
        for (int t = 0; t < 2; t++) {
            if (BL) ldsm4(bf[1][t], sbase + bLdNT + t * UP_BT_NT + 32);
            else    ldsm4t(bf[1][t], sbase + bLdNN + t * UP_BT_NN + 16 * 144);
        }
#pragma unroll
        for (int ks = 0; ks < 2; ks++)
#pragma unroll
            for (int mi = 0; mi < 4; mi++)
#pragma unroll
                for (int t = 0; t < 2; t++)
#pragma unroll
                    for (int j = 0; j < 2; j++) {
                        uint32_t b2[2] = { bf[ks][t][j * 2], bf[ks][t][j * 2 + 1] };
                        mma16(acc[mi][t * 2 + j], af[ks][mi], b2);
                    }
    }

    // ---- epilogue: GLU across halves, half2 stores
    int g = lane >> 2, q = lane & 3;
#pragma unroll
    for (int mi = 0; mi < 4; mi++) {
        int r0 = bm + wm * 64 + mi * 16 + g;
        int r1 = r0 + 8;
        long o0 = -1, o1 = -1;
        float w0 = 1.f, w1 = 1.f;
        if (EPI == 1) { o0 = r0; o1 = r1; }
        else {
            if (r0 < cnt) { o0 = (long)e * T_TOK + r0; w0 = g_w[e * T_TOK + r0]; }
            if (r1 < cnt) { o1 = (long)e * T_TOK + r1; w1 = g_w[e * T_TOK + r1]; }
        }
#pragma unroll
        for (int j = 0; j < 2; j++) {
            int col = c0 + wn * 16 + j * 8 + 2 * q;
            float p0 = acc[mi][j][0],     p1 = acc[mi][j][1];
            float p2 = acc[mi][j][2],     p3 = acc[mi][j][3];
            float g0 = acc[mi][2 + j][0], g1 = acc[mi][2 + j][1];
            float g2 = acc[mi][2 + j][2], g3 = acc[mi][2 + j][3];
            if (o0 >= 0) {
                float v0 = (EPI == 1) ? silu_f(p0) * g0 : silu_f(g0) * p0 * w0;
                float v1 = (EPI == 1) ? silu_f(p1) * g1 : silu_f(g1) * p1 * w0;
                *(__half2*)&C[o0 * I_DIM + col] = __floats2half2_rn(v0, v1);
            }
            if (o1 >= 0) {
                float v0 = (EPI == 1) ? silu_f(p2) * g2 : silu_f(g2) * p2 * w1;
                float v1 = (EPI == 1) ? silu_f(p3) * g3 : silu_f(g3) * p3 * w1;
                *(__half2*)&C[o1 * I_DIM + col] = __floats2half2_rn(v0, v1);
            }
        }
    }
}

// ================= DOWN GEMM: 128x128, BK=32, 256 threads ======================
// BL 0 (NN): B=[K][N] expert Wo, scatter rows to g_par (EPI 3).
// BL 1 (NT): B=[N][K] shared sWo, out = acc + par pair (EPI 4).
#define D_ASTR 80u
#define D_ATILE 10240u
#define D_BT_NT 10240u
#define D_BT_NN 8704u

template <int BL, int EPI>
__global__ void __launch_bounds__(256, 2)
down_gemm(const __half* __restrict__ Ab, const __half* __restrict__ Bb,
          float* __restrict__ C) {
    constexpr int N = H_DIM, K = I_DIM, NC = K / 32;
    constexpr uint32_t BT = BL ? D_BT_NT : D_BT_NN;
    constexpr uint32_t SSB = D_ATILE + BT;
    constexpr int GRP = (EPI == 3);

    int e   = GRP ? blockIdx.z : 0;
    int cnt = GRP ? g_count[e] : T_TOK;
    int bm  = blockIdx.y * 128;
    if (bm >= cnt) return;
    int bn  = blockIdx.x * 128;

    extern __shared__ char smc[];
    uint32_t smaddr = (uint32_t)__cvta_generic_to_shared(smc);
    int tid = threadIdx.x;

    int am = tid >> 1, as0 = (tid & 1) * 2;
    int apos = bm + am;
    long arow = GRP ? ((long)e * T_TOK + ((apos < cnt) ? apos : 0)) : apos;
    const __half* aSrc = Ab + (size_t)arow * K + as0 * 8;
    uint32_t aDst = (uint32_t)am * D_ASTR + as0 * 16;

    const __half* bSrc;
    uint32_t bDst;
    if (BL) {
        int nr = tid >> 1;
        bSrc = Bb + (size_t)(bn + nr) * K + as0 * 8;
        bDst = D_ATILE + (uint32_t)nr * D_ASTR + as0 * 16;
    } else {
        int kr = tid >> 3, bseg = tid & 7;
        bSrc = Bb + (size_t)e * K * N + (size_t)kr * N + bn + bseg * 8;
        bDst = D_ATILE + (uint32_t)kr * 272 + bseg * 16;
    }

    float acc[4][4][4];
#pragma unroll
    for (int i = 0; i < 4; i++)
#pragma unroll
        for (int j = 0; j < 4; j++)
#pragma unroll
            for (int q = 0; q < 4; q++) acc[i][j][q] = 0.f;

#pragma unroll
    for (int s = 0; s < 2; s++) {
        uint32_t base = smaddr + s * SSB;
        cpa16(base + aDst,      aSrc + s * 32);
        cpa16(base + aDst + 16, aSrc + s * 32 + 8);
        if (BL) {
            cpa16(base + bDst,      bSrc + s * 32);
            cpa16(base + bDst + 16, bSrc + s * 32 + 8);
        } else {
            cpa16(base + bDst,       bSrc + (size_t)s * 32 * N);
            cpa16(base + bDst + 128, bSrc + (size_t)s * 32 * N + 64);
        }
        cpa_commit();
    }

    int warp = tid >> 5, lane = tid & 31;
    int wm = warp >> 2, wn = warp & 3;

    uint32_t aLd = (uint32_t)(wm * 64 + (lane & 15)) * D_ASTR + (lane >> 4) * 16;
    uint32_t bLdNT = D_ATILE + (uint32_t)(wn * 32 + (lane & 7) + ((lane >> 4) * 8)) * D_ASTR +
                     ((lane >> 3) & 1) * 16;
    uint32_t bLdNN = D_ATILE + (uint32_t)(lane & 15) * 272 + (wn * 4 + (lane >> 4)) * 16;

    for (int c = 0; c < NC; c++) {
        cpa_wait<1>();
        __syncthreads();

        int pf = c + 2;
        if (pf < NC) {
            uint32_t base = smaddr + (uint32_t)(pf % 3) * SSB;
            cpa16(base + aDst,      aSrc + pf * 32);
            cpa16(base + aDst + 16, aSrc + pf * 32 + 8);
            if (BL) {
                cpa16(base + bDst,      bSrc + pf * 32);
                cpa16(base + bDst + 16, bSrc + pf * 32 + 8);
            } else {
                cpa16(base + bDst,       bSrc + (size_t)pf * 32 * N);
                cpa16(base + bDst + 128, bSrc + (size_t)pf * 32 * N + 64);
            }
        }
        cpa_commit();

        uint32_t sbase = smaddr + (uint32_t)(c % 3) * SSB;

        uint32_t af[2][4][4], bf[2][2][4];
#pragma unroll
        for (int mi = 0; mi < 4; mi++)
            ldsm4(af[0][mi], sbase + aLd + mi * (16 * D_ASTR));
#pragma unroll
        for (int p = 0; p < 2; p++) {
            if (BL) ldsm4(bf[0][p], sbase + bLdNT + p * (16 * D_ASTR));
            else    ldsm4t(bf[0][p], sbase + bLdNN + p * 32);
        }
#pragma unroll
        for (int mi = 0; mi < 4; mi++)
            ldsm4(af[1][mi], sbase + aLd + mi * (16 * D_ASTR) + 32);
#pragma unroll
        for (int p = 0; p < 2; p++) {
            if (BL) ldsm4(bf[1][p], sbase + bLdNT + p * (16 * D_ASTR) + 32);
            else    ldsm4t(bf[1][p], sbase + bLdNN + 16 * 272 + p * 32);
        }
#pragma unroll
        for (int ks = 0; ks < 2; ks++)
#pragma unroll
            for (int mi = 0; mi < 4; mi++)
#pragma unroll
                for (int ni = 0; ni < 4; ni++) {
                    uint32_t b2[2] = { bf[ks][ni >> 1][(ni & 1) * 2],
                                       bf[ks][ni >> 1][(ni & 1) * 2 + 1] };
                    mma16(acc[mi][ni], af[ks][mi], b2);
                }
    }

    int g = lane >> 2, q = lane & 3;
    if (EPI == 3) {
#pragma unroll
        for (int mi = 0; mi < 4; mi++) {
            int r0 = bm + wm * 64 + mi * 16 + g;
            int r1 = r0 + 8;
            long o0 = (r0 < cnt) ? (long)g_dst[e * T_TOK + r0] : -1;
            long o1 = (r1 < cnt) ? (long)g_dst[e * T_TOK + r1] : -1;
#pragma unroll
            for (int ni = 0; ni < 4; ni++) {
                int cx = bn + wn * 32 + ni * 8 + 2 * q;
                if (o0 >= 0) {
                    float2 v = { acc[mi][ni][0], acc[mi][ni][1] };
                    *(float2*)&C[o0 * H_DIM + cx] = v;
                }
                if (o1 >= 0) {
                    float2 v = { acc[mi][ni][2], acc[mi][ni][3] };
                    *(float2*)&C[o1 * H_DIM + cx] = v;
                }
            }
        }
    } else {
#pragma unroll
        for (int mi = 0; mi < 4; mi++) {
            int r0 = bm + wm * 64 + mi * 16 + g;
            int r1 = r0 + 8;
#pragma unroll
            for (int ni = 0; ni < 4; ni++) {
                int cx = bn + wn * 32 + ni * 8 + 2 * q;
                {
                    float2 p0 = *(float2*)&g_par[(size_t)(2 * r0) * H_DIM + cx];
                    float2 p1 = *(float2*)&g_par[(size_t)(2 * r0 + 1) * H_DIM + cx];
                    float2 v = { acc[mi][ni][0] + p0.x + p1.x,
                                 acc[mi][ni][1] + p0.y + p1.y };
                    *(float2*)&C[(size_t)r0 * H_DIM + cx] = v;
                }
                {
                    float2 p0 = *(float2*)&g_par[(size_t)(2 * r1) * H_DIM + cx];
                    float2 p1 = *(float2*)&g_par[(size_t)(2 * r1 + 1) * H_DIM + cx];
                    float2 v = { acc[mi][ni][2] + p0.x + p1.x,
                                 acc[mi][ni][3] + p0.y + p1.y };
                    *(float2*)&C[(size_t)r1 * H_DIM + cx] = v;
                }
            }
        }
    }
}

// ---------------- launch ---------------------------------------------------------
extern "C" void kernel_launch(void* const* d_in, const int* in_sizes, int n_in,
                              void* d_out, int out_size) {
    const float* x      = (const float*)d_in[0];
    const float* gate_w = (const float*)d_in[1];
    const float* bias   = (const float*)d_in[2];
    const float* Wi     = (const float*)d_in[3];
    const float* Wo     = (const float*)d_in[4];
    const float* sWi    = (const float*)d_in[5];
    const float* sWo    = (const float*)d_in[6];
    float* out = (float*)d_out;

    __half *p_act, *p_as, *p_hx, *p_hwi, *p_hwo, *p_hswi, *p_hswo;
    float* p_par;
    cudaGetSymbolAddress((void**)&p_act,  g_act);
    cudaGetSymbolAddress((void**)&p_as,   g_as);
    cudaGetSymbolAddress((void**)&p_par,  g_par);
    cudaGetSymbolAddress((void**)&p_hx,   g_hx);
    cudaGetSymbolAddress((void**)&p_hwi,  g_hwi);
    cudaGetSymbolAddress((void**)&p_hwo,  g_hwo);
    cudaGetSymbolAddress((void**)&p_hswi, g_hswi);
    cudaGetSymbolAddress((void**)&p_hswo, g_hswo);

    const int SMEM_UP_NT = 3 * (UP_ATILE + 2 * UP_BT_NT);  // 61440
    const int SMEM_UP_NN = 3 * (UP_ATILE + 2 * UP_BT_NN);  // 58368
    const int SMEM_DN_NN = 3 * (D_ATILE + D_BT_NN);        // 56832
    const int SMEM_DN_NT = 3 * (D_ATILE + D_BT_NT);        // 61440

    cudaFuncSetAttribute(up_gemm<1, 1>, cudaFuncAttributeMaxDynamicSharedMemorySize, SMEM_UP_NT);
    cudaFuncSetAttribute(up_gemm<0, 2>, cudaFuncAttributeMaxDynamicSharedMemorySize, SMEM_UP_NN);
    cudaFuncSetAttribute(down_gemm<0, 3>, cudaFuncAttributeMaxDynamicSharedMemorySize, SMEM_DN_NN);
    cudaFuncSetAttribute(down_gemm<1, 4>, cudaFuncAttributeMaxDynamicSharedMemorySize, SMEM_DN_NT);

    zero_counts_kernel<<<1, 32>>>();
    gating_kernel<<<T_TOK / 8, 256>>>(x, gate_w, bias);

    f2h_all_kernel<<<(int)((N8_TOT + 255) / 256), 256>>>(x, Wi, Wo, sWi, sWo);

    // shared up + GLU -> g_as  (NT split-B)
    up_gemm<1, 1><<<dim3(I_DIM / 64, T_TOK / 128), 256, SMEM_UP_NT>>>(p_hx, p_hswi, p_as);
    // expert up + GLU*w -> g_act  (NN split-B, gather)
    up_gemm<0, 2><<<dim3(I_DIM / 64, T_TOK / 128, E_NUM), 256, SMEM_UP_NN>>>(p_hx, p_hwi, p_act);
    // expert down -> g_par (NN, scatter)
    down_gemm<0, 3><<<dim3(H_DIM / 128, T_TOK / 128, E_NUM), 256, SMEM_DN_NN>>>(p_act, p_hwo, p_par);
    // shared down + final add -> out (NT)
    down_gemm<1, 4><<<dim3(H_DIM / 128, T_TOK / 128), 256, SMEM_DN_NT>>>(p_as, p_hswo, out);
}